// round 3
// baseline (speedup 1.0000x reference)
#include <cuda_runtime.h>
#include <stdint.h>

#define BB 8
#define HH 640
#define WW 640
#define NBOX 12
#define PP 256
#define IMG_ELEMS (HH*WW*3)      /* 1228800 */
#define PATCH_ELEMS (PP*PP*3)    /* 196608  */

struct BoxF {                       // 12 words
    float cc, ca, sa, top, phm1, sfac, delta;
    unsigned kn0, kn1;
    int xlo, xhi, _pad;
};

__device__ BoxF g_boxf[BB][NBOX];
__device__ int4 g_bbox[BB][NBOX];   // ylo,yhi,xlo,xhi inclusive; empty if ylo>yhi
__device__ float g_wb[BB][8];       // wm0..2, bd0..2
__device__ float g_part_img[1024];  // 128 per image
__device__ float g_part_p1[256];    // 32 per image
__device__ float g_patch[BB][PATCH_ELEMS];

// ---------------- threefry2x32 (JAX-exact, partitionable mode) ----------------
__device__ __forceinline__ void tf2x32(unsigned k0, unsigned k1,
                                       unsigned x0, unsigned x1,
                                       unsigned &o0, unsigned &o1) {
    unsigned ks2 = k0 ^ k1 ^ 0x1BD11BDAu;
    x0 += k0; x1 += k1;
#define TF_R(r) { x0 += x1; x1 = (x1 << (r)) | (x1 >> (32 - (r))); x1 ^= x0; }
    TF_R(13) TF_R(15) TF_R(26) TF_R(6)
    x0 += k1;  x1 += ks2 + 1u;
    TF_R(17) TF_R(29) TF_R(16) TF_R(24)
    x0 += ks2; x1 += k0 + 2u;
    TF_R(13) TF_R(15) TF_R(26) TF_R(6)
    x0 += k0;  x1 += k1 + 3u;
    TF_R(17) TF_R(29) TF_R(16) TF_R(24)
    x0 += k1;  x1 += ks2 + 4u;
    TF_R(13) TF_R(15) TF_R(26) TF_R(6)
    x0 += ks2; x1 += k0 + 5u;
#undef TF_R
    o0 = x0; o1 = x1;
}
__device__ __forceinline__ unsigned rbits32(unsigned k0, unsigned k1, unsigned idx) {
    unsigned a, b; tf2x32(k0, k1, 0u, idx, a, b); return a ^ b;
}
__device__ __forceinline__ void subkey(unsigned k0, unsigned k1, unsigned j,
                                       unsigned &s0, unsigned &s1) {
    tf2x32(k0, k1, 0u, j, s0, s1);
}
__device__ __forceinline__ float u01f(unsigned bits) {
    return __uint_as_float((bits >> 9) | 0x3f800000u) - 1.0f;
}
__device__ __forceinline__ float erfinv_xla(float x) {
    float xx = __fmul_rn(x, x);
    float w = -log1pf(-xx);
    float p;
    if (w < 5.0f) {
        w = __fsub_rn(w, 2.5f);
        p = 2.81022636e-08f;
        p = __fadd_rn(__fmul_rn(p, w), 3.43273939e-07f);
        p = __fadd_rn(__fmul_rn(p, w), -3.5233877e-06f);
        p = __fadd_rn(__fmul_rn(p, w), -4.39150654e-06f);
        p = __fadd_rn(__fmul_rn(p, w), 0.00021858087f);
        p = __fadd_rn(__fmul_rn(p, w), -0.00125372503f);
        p = __fadd_rn(__fmul_rn(p, w), -0.00417768164f);
        p = __fadd_rn(__fmul_rn(p, w), 0.246640727f);
        p = __fadd_rn(__fmul_rn(p, w), 1.50140941f);
    } else {
        w = __fsub_rn(__fsqrt_rn(w), 3.0f);
        p = -0.000200214257f;
        p = __fadd_rn(__fmul_rn(p, w), 0.000100950558f);
        p = __fadd_rn(__fmul_rn(p, w), 0.00134934322f);
        p = __fadd_rn(__fmul_rn(p, w), -0.00367342844f);
        p = __fadd_rn(__fmul_rn(p, w), 0.00573950773f);
        p = __fadd_rn(__fmul_rn(p, w), -0.0076224613f);
        p = __fadd_rn(__fmul_rn(p, w), 0.00943887047f);
        p = __fadd_rn(__fmul_rn(p, w), 1.00167406f);
        p = __fadd_rn(__fmul_rn(p, w), 2.83297682f);
    }
    return __fmul_rn(p, x);
}
__device__ __forceinline__ float normal_elem(unsigned k0, unsigned k1, int i) {
    unsigned bits = rbits32(k0, k1, (unsigned)i);
    const float lo = -0.99999994f;
    float span = __fsub_rn(1.0f, lo);
    float u = u01f(bits);
    float uu = fmaxf(lo, __fadd_rn(__fmul_rn(u, span), lo));
    return __fmul_rn(1.41421356237f, erfinv_xla(uu));
}

// ================= K0: setup (1 block) — all threefry-derived scalars =========
__global__ void k_setup(const float* __restrict__ boxes,
                        const float* __restrict__ scale_p) {
    int t = threadIdx.x;
    if (t >= 96 && t < 104) {               // wm/bd for image b
        int b = t - 96;
        unsigned i0, i1; subkey(0u, 42u, (unsigned)b, i0, i1);
        unsigned kw0, kw1, kb0, kb1;
        subkey(i0, i1, 0u, kw0, kw1);
        subkey(i0, i1, 1u, kb0, kb1);
#pragma unroll
        for (int c = 0; c < 3; c++) {
            g_wb[b][c]   = __fadd_rn(0.5f, __fmul_rn(0.1f, normal_elem(kw0, kw1, c)));
            g_wb[b][3+c] = __fmul_rn(0.01f, normal_elem(kb0, kb1, c));
        }
        return;
    }
    if (t >= BB * NBOX) return;
    float scale = *scale_p;
    int b = t / NBOX, j = t % NBOX;
    unsigned i0, i1; subkey(0u, 42u, (unsigned)b, i0, i1);
    unsigned s0, s1; subkey(i0, i1, 2u, s0, s1);
    unsigned bk0, bk1; subkey(s0, s1, (unsigned)j, bk0, bk1);
    unsigned kc10,kc11,kc20,kc21,ka0,ka1,kd0,kd1,kn0,kn1;
    subkey(bk0,bk1,0u,kc10,kc11);
    subkey(bk0,bk1,1u,kc20,kc21);
    subkey(bk0,bk1,2u,ka0,ka1);
    subkey(bk0,bk1,3u,kd0,kd1);
    subkey(bk0,bk1,4u,kn0,kn1);
    float u1 = u01f(rbits32(kc10,kc11,0u));
    float u2 = u01f(rbits32(kc20,kc21,0u));
    float ua = u01f(rbits32(ka0,ka1,0u));
    float ud = u01f(rbits32(kd0,kd1,0u));

    const float* bx = boxes + (b*NBOX + j)*4;
    float ymin = bx[0], xmin = bx[1], ymax = bx[2], xmax = bx[3];
    float h = __fsub_rn(ymax, ymin);
    float w = __fsub_rn(xmax, xmin);
    float longer = fmaxf(h, w);
    float patch_size = floorf(__fmul_rn(longer, scale));
    float diag = fminf(__fmul_rn(1.41421356237f, patch_size), 640.0f);
    float jy = __fmul_rn(__fmul_rn(__fsub_rn(u1, 0.5f), 0.2f), h);
    float jx = __fmul_rn(__fmul_rn(__fsub_rn(u2, 0.5f), 0.2f), w);
    float oy = __fadd_rn(__fadd_rn(ymin, __fmul_rn(h, 0.5f)), jy);
    float ox = __fadd_rn(__fadd_rn(xmin, __fmul_rn(w, 0.5f)), jx);
    float ymin_p = fmaxf(__fsub_rn(oy, __fmul_rn(diag, 0.5f)), 0.0f);
    float xmin_p = fmaxf(__fsub_rn(ox, __fmul_rn(diag, 0.5f)), 0.0f);
    if (__fadd_rn(ymin_p, diag) > 640.0f) ymin_p = __fsub_rn(640.0f, diag);
    if (__fadd_rn(xmin_p, diag) > 640.0f) xmin_p = __fsub_rn(640.0f, diag);
    int valid = (__fmul_rn(patch_size, patch_size) > 4.0f) ? 1 : 0;
    float y0f = floorf(ymin_p), x0f = floorf(xmin_p);
    float phf = patch_size;
    float diagf = floorf(diag);
    float top = floorf(__fmul_rn(__fsub_rn(diagf, phf), 0.5f));
    float angle = __fmul_rn(__fsub_rn(__fmul_rn(ua, 2.0f), 1.0f),
                            0.34906585039886593f);
    float delta = __fmul_rn(__fsub_rn(__fmul_rn(ud, 2.0f), 1.0f), 0.3f);
    float ca = cosf(angle), sa = sinf(angle);
    float cc = __fmul_rn(__fsub_rn(diagf, 1.0f), 0.5f);
    float safe_ph = fmaxf(phf, 1.0f);
    float sfac = __fdiv_rn(256.0f, safe_ph);

    int ylo, yhi, xlo, xhi;
    if (valid) {
        ylo = (int)y0f; xlo = (int)x0f;
        int d = (int)diagf;
        yhi = ylo + d - 1; xhi = xlo + d - 1;
    } else {
        ylo = 1; yhi = 0; xlo = 1; xhi = 0;
    }
    BoxF bf;
    bf.cc = cc; bf.ca = ca; bf.sa = sa; bf.top = top;
    bf.phm1 = __fsub_rn(phf, 1.0f);
    bf.sfac = sfac; bf.delta = delta;
    bf.kn0 = kn0; bf.kn1 = kn1;
    bf.xlo = xlo; bf.xhi = xhi; bf._pad = 0;
    g_boxf[b][j] = bf;
    g_bbox[b][j] = make_int4(ylo, yhi, xlo, xhi);
}

// ================= K1: partial sums (lean, high-MLP) ==========================
// blocks 0..1023: image partials; 1024..1279: adjusted-patch partials
__global__ void __launch_bounds__(256) k_partials(const float* __restrict__ images,
                                                  const float* __restrict__ patch) {
    __shared__ float sh[256];
    int blk = blockIdx.x;
    int t = threadIdx.x;
    float acc = 0.f;

    if (blk < 1024) {
        const float4* base = (const float4*)(images
                              + (size_t)(blk >> 7) * IMG_ELEMS + (blk & 127) * 9600);
        float4 v0 = base[t], v1 = base[t+256], v2 = base[t+512], v3 = base[t+768];
        acc += ((v0.x+v0.y)+(v0.z+v0.w));
        acc += ((v1.x+v1.y)+(v1.z+v1.w));
        acc += ((v2.x+v2.y)+(v2.z+v2.w));
        acc += ((v3.x+v3.y)+(v3.z+v3.w));
        float4 w0 = base[t+1024], w1 = base[t+1280], w2 = base[t+1536], w3 = base[t+1792];
        acc += ((w0.x+w0.y)+(w0.z+w0.w));
        acc += ((w1.x+w1.y)+(w1.z+w1.w));
        acc += ((w2.x+w2.y)+(w2.z+w2.w));
        acc += ((w3.x+w3.y)+(w3.z+w3.w));
        float4 z0 = base[t+2048];
        acc += ((z0.x+z0.y)+(z0.z+z0.w));
        if (t < 96) {
            float4 z1 = base[t+2304];
            acc += ((z1.x+z1.y)+(z1.z+z1.w));
        }
        sh[t] = acc; __syncthreads();
        for (int o = 128; o > 0; o >>= 1) {
            if (t < o) sh[t] += sh[t + o];
            __syncthreads();
        }
        if (t == 0) g_part_img[blk] = sh[0];
        return;
    }

    int r = blk - 1024;
    int b = r >> 5, s = r & 31;
    float wm0 = g_wb[b][0], wm1 = g_wb[b][1], wm2 = g_wb[b][2];
    float bd0 = g_wb[b][3], bd1 = g_wb[b][4], bd2 = g_wb[b][5];
    int start = s * 6144;
    const float4* base = (const float4*)(patch + start);
    float4 q[6];
#pragma unroll
    for (int k = 0; k < 6; k++) q[k] = base[t + 256*k];
#pragma unroll
    for (int k = 0; k < 6; k++) {
        int e = start + (t + 256*k) * 4;
        float vv[4] = {q[k].x, q[k].y, q[k].z, q[k].w};
#pragma unroll
        for (int m = 0; m < 4; m++) {
            int c = (e + m) % 3;
            float wmv = c == 0 ? wm0 : (c == 1 ? wm1 : wm2);
            float bdv = c == 0 ? bd0 : (c == 1 ? bd1 : bd2);
            float x = __fadd_rn(__fmul_rn(wmv, vv[m]), bdv);
            acc += fminf(fmaxf(x, -1.0f), 1.0f);
        }
    }
    sh[t] = acc; __syncthreads();
    for (int o = 128; o > 0; o >>= 1) {
        if (t < o) sh[t] += sh[t + o];
        __syncthreads();
    }
    if (t == 0) g_part_p1[r] = sh[0];
}

// ================= K2: per-block redundant offset + build adjusted patch ======
__global__ void __launch_bounds__(256) k_build(const float* __restrict__ patch) {
    __shared__ float sh[160];
    int blk = blockIdx.x;
    int b = blk / 96, s = blk % 96;
    int t = threadIdx.x;
    if (t < 128) sh[t] = g_part_img[b*128 + t];
    else if (t < 160) sh[t] = g_part_p1[b*32 + (t - 128)];
    __syncthreads();
    if (t == 0) { float a = 0.f; for (int i = 0; i < 128; i++) a += sh[i]; sh[0] = a; }
    if (t == 1) { float a = 0.f; for (int i = 0; i < 32; i++) a += sh[128+i]; sh[1] = a; }
    __syncthreads();
    float offset;
    {
        float mi = __fdiv_rn(sh[0], 1228800.0f);
        float mp = __fdiv_rn(sh[1], 196608.0f);
        offset = __fsub_rn(mi, mp);
    }
    float wm0 = g_wb[b][0], wm1 = g_wb[b][1], wm2 = g_wb[b][2];
    float bd0 = g_wb[b][3], bd1 = g_wb[b][4], bd2 = g_wb[b][5];

    int start = s * 2048;
    const float4* src = (const float4*)(patch + start);
    float4* dst = (float4*)(&g_patch[b][start]);
#pragma unroll
    for (int ii = 0; ii < 2; ii++) {
        int i = t + 256*ii;
        float4 v = src[i];
        int e = start + i * 4;
        float vv[4] = {v.x, v.y, v.z, v.w};
        float rr[4];
#pragma unroll
        for (int k = 0; k < 4; k++) {
            int c = (e + k) % 3;
            float wmv = c == 0 ? wm0 : (c == 1 ? wm1 : wm2);
            float bdv = c == 0 ? bd0 : (c == 1 ? bd1 : bd2);
            float x = __fadd_rn(__fmul_rn(wmv, vv[k]), bdv);
            x = fminf(fmaxf(x, -1.0f), 1.0f);
            x = __fadd_rn(x, offset);
            rr[k] = fminf(fmaxf(x, -1.0f), 1.0f);
        }
        dst[i] = make_float4(rr[0], rr[1], rr[2], rr[3]);
    }
}

// ================= K3: main pass, 8 px / thread, strip hit-mask ===============
__global__ void __launch_bounds__(256) k_main(const float4* __restrict__ img4,
                                              float4* __restrict__ out4,
                                              float* __restrict__ outf_base) {
    __shared__ int4 sbb[NBOX];
    __shared__ BoxF sbf[NBOX];
    int b = blockIdx.x / 200;     // 200 blocks per image
    if (threadIdx.x < NBOX) sbb[threadIdx.x] = g_bbox[b][threadIdx.x];
    {
        const unsigned* src = (const unsigned*)(&g_boxf[b][0]);
        unsigned* dst = (unsigned*)(&sbf[0]);
        for (int i = threadIdx.x; i < NBOX * 12; i += 256) dst[i] = src[i];
    }
    __syncthreads();
    int gid = blockIdx.x * 256 + threadIdx.x;   // strip id; 8 px per strip
    int pix = gid * 8 - b * (HH * WW);
    int y = pix / WW;
    int x = pix - y * WW;

    size_t v = (size_t)gid * 6;
    // copy-through first (frees registers before heavy path)
    out4[v+0] = img4[v+0]; out4[v+1] = img4[v+1]; out4[v+2] = img4[v+2];
    out4[v+3] = img4[v+3]; out4[v+4] = img4[v+4]; out4[v+5] = img4[v+5];

    int hit = 0;
#pragma unroll
    for (int j = 0; j < NBOX; j++) {
        int4 bb = sbb[j];
        if (y >= bb.x && y <= bb.y && x <= bb.w && x + 7 >= bb.z) hit |= (1 << j);
    }
    if (!hit) return;

    const float* pb = g_patch[b];
    float* outf = outf_base + (size_t)gid * 24;

#pragma unroll 1
    for (int p = 0; p < 8; p++) {
        int xp = x + p;
#pragma unroll 1
        for (int j = NBOX - 1; j >= 0; --j) {
            if (!(hit & (1 << j))) continue;
            int4 bb = sbb[j];
            if (xp < bb.z || xp > bb.w) continue;
            // u,v exact: y0f/x0f are integer-valued
            float u = (float)(y - bb.x);
            float vv = (float)(xp - bb.z);
            float cc = sbf[j].cc, ca = sbf[j].ca, sa = sbf[j].sa;
            float top = sbf[j].top, phm1 = sbf[j].phm1;
            float vc = __fsub_rn(vv, cc);
            float uc = __fsub_rn(u, cc);
            float sv = __fadd_rn(__fsub_rn(__fmul_rn(ca, vc), __fmul_rn(sa, uc)), cc);
            float su = __fadd_rn(__fadd_rn(__fmul_rn(sa, vc), __fmul_rn(ca, uc)), cc);
            float ry = __fsub_rn(su, top);
            float rx = __fsub_rn(sv, top);
            if (!(ry >= 0.0f && ry <= phm1 && rx >= 0.0f && rx <= phm1)) continue;

            float sfac = sbf[j].sfac, delta = sbf[j].delta;
            unsigned kn0 = sbf[j].kn0, kn1 = sbf[j].kn1;
            float py = __fsub_rn(__fmul_rn(__fadd_rn(ry, 0.5f), sfac), 0.5f);
            float px = __fsub_rn(__fmul_rn(__fadd_rn(rx, 0.5f), sfac), 0.5f);
            float fy = floorf(py), fx = floorf(px);
            float wy = __fsub_rn(py, fy), wx = __fsub_rn(px, fx);
            int y0i = (int)fy; y0i = y0i < 0 ? 0 : (y0i > 255 ? 255 : y0i);
            int x0i = (int)fx; x0i = x0i < 0 ? 0 : (x0i > 255 ? 255 : x0i);
            int y1i = y0i + 1 > 255 ? 255 : y0i + 1;
            int x1i = x0i + 1 > 255 ? 255 : x0i + 1;
            int base00 = (y0i * 256 + x0i) * 3;
            int base01 = (y0i * 256 + x1i) * 3;
            int base10 = (y1i * 256 + x0i) * 3;
            int base11 = (y1i * 256 + x1i) * 3;
            float omwx = __fsub_rn(1.0f, wx), omwy = __fsub_rn(1.0f, wy);
            int mbase = (y * WW + xp) * 3;
#pragma unroll
            for (int c = 0; c < 3; c++) {
                float v00 = pb[base00 + c], v01 = pb[base01 + c];
                float v10 = pb[base10 + c], v11 = pb[base11 + c];
                float t0 = __fadd_rn(__fmul_rn(omwx, v00), __fmul_rn(wx, v01));
                float t1 = __fadd_rn(__fmul_rn(omwx, v10), __fmul_rn(wx, v11));
                float bil = __fadd_rn(__fmul_rn(omwy, t0), __fmul_rn(wy, t1));
                unsigned bits = rbits32(kn0, kn1, (unsigned)(mbase + c));
                float nz = fmaxf(-0.01f, __fadd_rn(__fmul_rn(u01f(bits), 0.02f), -0.01f));
                float val = __fadd_rn(__fadd_rn(bil, nz), delta);
                outf[p * 3 + c] = fminf(fmaxf(val, -1.0f), 1.0f);
            }
            break;   // highest j wins
        }
    }
}

extern "C" void kernel_launch(void* const* d_in, const int* in_sizes, int n_in,
                              void* d_out, int out_size) {
    const float *images = nullptr, *boxes = nullptr, *patch = nullptr, *scalep = nullptr;
    for (int i = 0; i < n_in; i++) {
        if      (in_sizes[i] == BB * IMG_ELEMS)  images = (const float*)d_in[i];
        else if (in_sizes[i] == BB * NBOX * 4)   boxes  = (const float*)d_in[i];
        else if (in_sizes[i] == PATCH_ELEMS)     patch  = (const float*)d_in[i];
        else if (in_sizes[i] == 1)               scalep = (const float*)d_in[i];
    }
    k_setup<<<1, 128>>>(boxes, scalep);
    k_partials<<<1280, 256>>>(images, patch);
    k_build<<<768, 256>>>(patch);
    k_main<<<1600, 256>>>((const float4*)images, (float4*)d_out, (float*)d_out);
}

// round 5
// speedup vs baseline: 2.9139x; 2.9139x over previous
#include <cuda_runtime.h>
#include <stdint.h>

#define BB 8
#define HH 640
#define WW 640
#define NBOX 12
#define PP 256
#define IMG_ELEMS (HH*WW*3)      /* 1228800 */
#define PATCH_ELEMS (PP*PP*3)    /* 196608  */

struct BoxF {                       // 12 words
    float cc, ca, sa, top, phm1, sfac, delta;
    unsigned kn0, kn1;
    int xlo, xhi, _pad;
};

__device__ BoxF g_boxf[BB][NBOX];
__device__ int4 g_bbox[BB][NBOX];   // ylo,yhi,xlo,xhi inclusive; empty if ylo>yhi
__device__ float g_wb[BB][8];       // wm0..2, bd0..2
__device__ float g_part_img[1024];  // 128 per image
__device__ float g_part_p1[256];    // 32 per image
__device__ float g_patch[BB][PATCH_ELEMS];

// ---------------- threefry2x32 (JAX-exact, partitionable mode) ----------------
__device__ __forceinline__ void tf2x32(unsigned k0, unsigned k1,
                                       unsigned x0, unsigned x1,
                                       unsigned &o0, unsigned &o1) {
    unsigned ks2 = k0 ^ k1 ^ 0x1BD11BDAu;
    x0 += k0; x1 += k1;
#define TF_R(r) { x0 += x1; x1 = (x1 << (r)) | (x1 >> (32 - (r))); x1 ^= x0; }
    TF_R(13) TF_R(15) TF_R(26) TF_R(6)
    x0 += k1;  x1 += ks2 + 1u;
    TF_R(17) TF_R(29) TF_R(16) TF_R(24)
    x0 += ks2; x1 += k0 + 2u;
    TF_R(13) TF_R(15) TF_R(26) TF_R(6)
    x0 += k0;  x1 += k1 + 3u;
    TF_R(17) TF_R(29) TF_R(16) TF_R(24)
    x0 += k1;  x1 += ks2 + 4u;
    TF_R(13) TF_R(15) TF_R(26) TF_R(6)
    x0 += ks2; x1 += k0 + 5u;
#undef TF_R
    o0 = x0; o1 = x1;
}
__device__ __forceinline__ unsigned rbits32(unsigned k0, unsigned k1, unsigned idx) {
    unsigned a, b; tf2x32(k0, k1, 0u, idx, a, b); return a ^ b;
}
__device__ __forceinline__ void subkey(unsigned k0, unsigned k1, unsigned j,
                                       unsigned &s0, unsigned &s1) {
    tf2x32(k0, k1, 0u, j, s0, s1);
}
__device__ __forceinline__ float u01f(unsigned bits) {
    return __uint_as_float((bits >> 9) | 0x3f800000u) - 1.0f;
}
__device__ __forceinline__ float erfinv_xla(float x) {
    float xx = __fmul_rn(x, x);
    float w = -log1pf(-xx);
    float p;
    if (w < 5.0f) {
        w = __fsub_rn(w, 2.5f);
        p = 2.81022636e-08f;
        p = __fadd_rn(__fmul_rn(p, w), 3.43273939e-07f);
        p = __fadd_rn(__fmul_rn(p, w), -3.5233877e-06f);
        p = __fadd_rn(__fmul_rn(p, w), -4.39150654e-06f);
        p = __fadd_rn(__fmul_rn(p, w), 0.00021858087f);
        p = __fadd_rn(__fmul_rn(p, w), -0.00125372503f);
        p = __fadd_rn(__fmul_rn(p, w), -0.00417768164f);
        p = __fadd_rn(__fmul_rn(p, w), 0.246640727f);
        p = __fadd_rn(__fmul_rn(p, w), 1.50140941f);
    } else {
        w = __fsub_rn(__fsqrt_rn(w), 3.0f);
        p = -0.000200214257f;
        p = __fadd_rn(__fmul_rn(p, w), 0.000100950558f);
        p = __fadd_rn(__fmul_rn(p, w), 0.00134934322f);
        p = __fadd_rn(__fmul_rn(p, w), -0.00367342844f);
        p = __fadd_rn(__fmul_rn(p, w), 0.00573950773f);
        p = __fadd_rn(__fmul_rn(p, w), -0.0076224613f);
        p = __fadd_rn(__fmul_rn(p, w), 0.00943887047f);
        p = __fadd_rn(__fmul_rn(p, w), 1.00167406f);
        p = __fadd_rn(__fmul_rn(p, w), 2.83297682f);
    }
    return __fmul_rn(p, x);
}
__device__ __forceinline__ float normal_elem(unsigned k0, unsigned k1, int i) {
    unsigned bits = rbits32(k0, k1, (unsigned)i);
    const float lo = -0.99999994f;
    float span = __fsub_rn(1.0f, lo);
    float u = u01f(bits);
    float uu = fmaxf(lo, __fadd_rn(__fmul_rn(u, span), lo));
    return __fmul_rn(1.41421356237f, erfinv_xla(uu));
}

// ================= K0: setup (1 block) — all threefry-derived scalars =========
__global__ void k_setup(const float* __restrict__ boxes,
                        const float* __restrict__ scale_p) {
    int t = threadIdx.x;
    if (t >= 96 && t < 104) {               // wm/bd for image b
        int b = t - 96;
        unsigned i0, i1; subkey(0u, 42u, (unsigned)b, i0, i1);
        unsigned kw0, kw1, kb0, kb1;
        subkey(i0, i1, 0u, kw0, kw1);
        subkey(i0, i1, 1u, kb0, kb1);
#pragma unroll
        for (int c = 0; c < 3; c++) {
            g_wb[b][c]   = __fadd_rn(0.5f, __fmul_rn(0.1f, normal_elem(kw0, kw1, c)));
            g_wb[b][3+c] = __fmul_rn(0.01f, normal_elem(kb0, kb1, c));
        }
        return;
    }
    if (t >= BB * NBOX) return;
    float scale = *scale_p;
    int b = t / NBOX, j = t % NBOX;
    unsigned i0, i1; subkey(0u, 42u, (unsigned)b, i0, i1);
    unsigned s0, s1; subkey(i0, i1, 2u, s0, s1);
    unsigned bk0, bk1; subkey(s0, s1, (unsigned)j, bk0, bk1);
    unsigned kc10,kc11,kc20,kc21,ka0,ka1,kd0,kd1,kn0,kn1;
    subkey(bk0,bk1,0u,kc10,kc11);
    subkey(bk0,bk1,1u,kc20,kc21);
    subkey(bk0,bk1,2u,ka0,ka1);
    subkey(bk0,bk1,3u,kd0,kd1);
    subkey(bk0,bk1,4u,kn0,kn1);
    float u1 = u01f(rbits32(kc10,kc11,0u));
    float u2 = u01f(rbits32(kc20,kc21,0u));
    float ua = u01f(rbits32(ka0,ka1,0u));
    float ud = u01f(rbits32(kd0,kd1,0u));

    const float* bx = boxes + (b*NBOX + j)*4;
    float ymin = bx[0], xmin = bx[1], ymax = bx[2], xmax = bx[3];
    float h = __fsub_rn(ymax, ymin);
    float w = __fsub_rn(xmax, xmin);
    float longer = fmaxf(h, w);
    float patch_size = floorf(__fmul_rn(longer, scale));
    float diag = fminf(__fmul_rn(1.41421356237f, patch_size), 640.0f);
    float jy = __fmul_rn(__fmul_rn(__fsub_rn(u1, 0.5f), 0.2f), h);
    float jx = __fmul_rn(__fmul_rn(__fsub_rn(u2, 0.5f), 0.2f), w);
    float oy = __fadd_rn(__fadd_rn(ymin, __fmul_rn(h, 0.5f)), jy);
    float ox = __fadd_rn(__fadd_rn(xmin, __fmul_rn(w, 0.5f)), jx);
    float ymin_p = fmaxf(__fsub_rn(oy, __fmul_rn(diag, 0.5f)), 0.0f);
    float xmin_p = fmaxf(__fsub_rn(ox, __fmul_rn(diag, 0.5f)), 0.0f);
    if (__fadd_rn(ymin_p, diag) > 640.0f) ymin_p = __fsub_rn(640.0f, diag);
    if (__fadd_rn(xmin_p, diag) > 640.0f) xmin_p = __fsub_rn(640.0f, diag);
    int valid = (__fmul_rn(patch_size, patch_size) > 4.0f) ? 1 : 0;
    float y0f = floorf(ymin_p), x0f = floorf(xmin_p);
    float phf = patch_size;
    float diagf = floorf(diag);
    float top = floorf(__fmul_rn(__fsub_rn(diagf, phf), 0.5f));
    float angle = __fmul_rn(__fsub_rn(__fmul_rn(ua, 2.0f), 1.0f),
                            0.34906585039886593f);
    float delta = __fmul_rn(__fsub_rn(__fmul_rn(ud, 2.0f), 1.0f), 0.3f);
    float ca = cosf(angle), sa = sinf(angle);
    float cc = __fmul_rn(__fsub_rn(diagf, 1.0f), 0.5f);
    float safe_ph = fmaxf(phf, 1.0f);
    float sfac = __fdiv_rn(256.0f, safe_ph);

    int ylo, yhi, xlo, xhi;
    if (valid) {
        ylo = (int)y0f; xlo = (int)x0f;
        int d = (int)diagf;
        yhi = ylo + d - 1; xhi = xlo + d - 1;
    } else {
        ylo = 1; yhi = 0; xlo = 1; xhi = 0;
    }
    BoxF bf;
    bf.cc = cc; bf.ca = ca; bf.sa = sa; bf.top = top;
    bf.phm1 = __fsub_rn(phf, 1.0f);
    bf.sfac = sfac; bf.delta = delta;
    bf.kn0 = kn0; bf.kn1 = kn1;
    bf.xlo = xlo; bf.xhi = xhi; bf._pad = 0;
    g_boxf[b][j] = bf;
    g_bbox[b][j] = make_int4(ylo, yhi, xlo, xhi);
}

// ============ K1: fused image copy + mean partials; patch partials ============
// blocks 0..1023: copy 9600-float segment AND accumulate its sum (float4)
// blocks 1024..1279: adjusted-patch mean partials
__global__ void __launch_bounds__(256) k_stream(const float4* __restrict__ img4,
                                                float4* __restrict__ out4,
                                                const float* __restrict__ patch) {
    __shared__ float sh[256];
    int blk = blockIdx.x;
    int t = threadIdx.x;
    float acc = 0.f;

    if (blk < 1024) {
        const float4* base = img4 + (size_t)blk * 2400;
        float4* obase = out4 + (size_t)blk * 2400;
        float4 v0 = base[t], v1 = base[t+256], v2 = base[t+512], v3 = base[t+768];
        obase[t] = v0; obase[t+256] = v1; obase[t+512] = v2; obase[t+768] = v3;
        acc += ((v0.x+v0.y)+(v0.z+v0.w));
        acc += ((v1.x+v1.y)+(v1.z+v1.w));
        acc += ((v2.x+v2.y)+(v2.z+v2.w));
        acc += ((v3.x+v3.y)+(v3.z+v3.w));
        float4 w0 = base[t+1024], w1 = base[t+1280], w2 = base[t+1536], w3 = base[t+1792];
        obase[t+1024] = w0; obase[t+1280] = w1; obase[t+1536] = w2; obase[t+1792] = w3;
        acc += ((w0.x+w0.y)+(w0.z+w0.w));
        acc += ((w1.x+w1.y)+(w1.z+w1.w));
        acc += ((w2.x+w2.y)+(w2.z+w2.w));
        acc += ((w3.x+w3.y)+(w3.z+w3.w));
        float4 z0 = base[t+2048];
        obase[t+2048] = z0;
        acc += ((z0.x+z0.y)+(z0.z+z0.w));
        if (t < 96) {
            float4 z1 = base[t+2304];
            obase[t+2304] = z1;
            acc += ((z1.x+z1.y)+(z1.z+z1.w));
        }
        sh[t] = acc; __syncthreads();
        for (int o = 128; o > 0; o >>= 1) {
            if (t < o) sh[t] += sh[t + o];
            __syncthreads();
        }
        if (t == 0) g_part_img[blk] = sh[0];
        return;
    }

    int r = blk - 1024;
    int b = r >> 5, s = r & 31;
    float wm0 = g_wb[b][0], wm1 = g_wb[b][1], wm2 = g_wb[b][2];
    float bd0 = g_wb[b][3], bd1 = g_wb[b][4], bd2 = g_wb[b][5];
    int start = s * 6144;
    const float4* base = (const float4*)(patch + start);
    float4 q[6];
#pragma unroll
    for (int k = 0; k < 6; k++) q[k] = base[t + 256*k];
#pragma unroll
    for (int k = 0; k < 6; k++) {
        int e = start + (t + 256*k) * 4;
        float vv[4] = {q[k].x, q[k].y, q[k].z, q[k].w};
#pragma unroll
        for (int m = 0; m < 4; m++) {
            int c = (e + m) % 3;
            float wmv = c == 0 ? wm0 : (c == 1 ? wm1 : wm2);
            float bdv = c == 0 ? bd0 : (c == 1 ? bd1 : bd2);
            float x = __fadd_rn(__fmul_rn(wmv, vv[m]), bdv);
            acc += fminf(fmaxf(x, -1.0f), 1.0f);
        }
    }
    sh[t] = acc; __syncthreads();
    for (int o = 128; o > 0; o >>= 1) {
        if (t < o) sh[t] += sh[t + o];
        __syncthreads();
    }
    if (t == 0) g_part_p1[r] = sh[0];
}

// ================= K2: per-block redundant offset + build adjusted patch ======
__global__ void __launch_bounds__(256) k_build(const float* __restrict__ patch) {
    __shared__ float sh[160];
    int blk = blockIdx.x;
    int b = blk / 96, s = blk % 96;
    int t = threadIdx.x;
    if (t < 128) sh[t] = g_part_img[b*128 + t];
    else if (t < 160) sh[t] = g_part_p1[b*32 + (t - 128)];
    __syncthreads();
    if (t == 0) { float a = 0.f; for (int i = 0; i < 128; i++) a += sh[i]; sh[0] = a; }
    if (t == 1) { float a = 0.f; for (int i = 0; i < 32; i++) a += sh[128+i]; sh[1] = a; }
    __syncthreads();
    float offset;
    {
        float mi = __fdiv_rn(sh[0], 1228800.0f);
        float mp = __fdiv_rn(sh[1], 196608.0f);
        offset = __fsub_rn(mi, mp);
    }
    float wm0 = g_wb[b][0], wm1 = g_wb[b][1], wm2 = g_wb[b][2];
    float bd0 = g_wb[b][3], bd1 = g_wb[b][4], bd2 = g_wb[b][5];

    int start = s * 2048;
    const float4* src = (const float4*)(patch + start);
    float4* dst = (float4*)(&g_patch[b][start]);
#pragma unroll
    for (int ii = 0; ii < 2; ii++) {
        int i = t + 256*ii;
        float4 v = src[i];
        int e = start + i * 4;
        float vv[4] = {v.x, v.y, v.z, v.w};
        float rr[4];
#pragma unroll
        for (int k = 0; k < 4; k++) {
            int c = (e + k) % 3;
            float wmv = c == 0 ? wm0 : (c == 1 ? wm1 : wm2);
            float bdv = c == 0 ? bd0 : (c == 1 ? bd1 : bd2);
            float x = __fadd_rn(__fmul_rn(wmv, vv[k]), bdv);
            x = fminf(fmaxf(x, -1.0f), 1.0f);
            x = __fadd_rn(x, offset);
            rr[k] = fminf(fmaxf(x, -1.0f), 1.0f);
        }
        dst[i] = make_float4(rr[0], rr[1], rr[2], rr[3]);
    }
}

// ================= K3: scatter — one thread per candidate patch pixel =========
// grid: 8 images x 12 boxes x 64 blocks (128x128 slot), 256 thr/block.
// thread (b, j, u, v); writes pixel iff box j's mask covers it AND no box k>j does.
__device__ __forceinline__ bool rot_ok(float cc, float ca, float sa, float top,
                                       float phm1, float fu, float fv,
                                       float& ry, float& rx) {
    float vc = __fsub_rn(fv, cc);
    float uc = __fsub_rn(fu, cc);
    float sv = __fadd_rn(__fsub_rn(__fmul_rn(ca, vc), __fmul_rn(sa, uc)), cc);
    float su = __fadd_rn(__fadd_rn(__fmul_rn(sa, vc), __fmul_rn(ca, uc)), cc);
    ry = __fsub_rn(su, top);
    rx = __fsub_rn(sv, top);
    return (ry >= 0.0f && ry <= phm1 && rx >= 0.0f && rx <= phm1);
}

__global__ void __launch_bounds__(256) k_scatter(float* __restrict__ out) {
    __shared__ int4 sbb[NBOX];
    __shared__ BoxF sbf[NBOX];
    int blk = blockIdx.x;
    int b = blk / 768;
    int r = blk - b * 768;
    int j = r >> 6;
    int s = r & 63;
    if (threadIdx.x < NBOX) sbb[threadIdx.x] = g_bbox[b][threadIdx.x];
    {
        const unsigned* src = (const unsigned*)(&g_boxf[b][0]);
        unsigned* dst = (unsigned*)(&sbf[0]);
        for (int i = threadIdx.x; i < NBOX * 12; i += 256) dst[i] = src[i];
    }
    __syncthreads();

    int tid = s * 256 + threadIdx.x;       // 0..16383
    int u = tid >> 7;                      // 0..127
    int v = tid & 127;
    int4 bb = sbb[j];
    int dI = bb.y - bb.x + 1;              // diag in pixels (<=0 if invalid)
    if (u >= dI || v >= dI) return;

    BoxF bf = sbf[j];
    float ry, rx;
    if (!rot_ok(bf.cc, bf.ca, bf.sa, bf.top, bf.phm1, (float)u, (float)v, ry, rx))
        return;

    int y = bb.x + u;
    int x = bb.z + v;

    // winner check: any box k > j covering (y,x) steals this pixel
#pragma unroll 1
    for (int k = j + 1; k < NBOX; k++) {
        int4 bk = sbb[k];
        if (y < bk.x || y > bk.y || x < bk.z || x > bk.w) continue;
        float r2, x2;
        BoxF bfk = sbf[k];
        if (rot_ok(bfk.cc, bfk.ca, bfk.sa, bfk.top, bfk.phm1,
                   (float)(y - bk.x), (float)(x - bk.z), r2, x2))
            return;
    }

    // heavy path: bilinear sample + noise + delta + clip, 3 channels
    const float* pb = g_patch[b];
    float py = __fsub_rn(__fmul_rn(__fadd_rn(ry, 0.5f), bf.sfac), 0.5f);
    float px = __fsub_rn(__fmul_rn(__fadd_rn(rx, 0.5f), bf.sfac), 0.5f);
    float fy = floorf(py), fx = floorf(px);
    float wy = __fsub_rn(py, fy), wx = __fsub_rn(px, fx);
    int y0i = (int)fy; y0i = y0i < 0 ? 0 : (y0i > 255 ? 255 : y0i);
    int x0i = (int)fx; x0i = x0i < 0 ? 0 : (x0i > 255 ? 255 : x0i);
    int y1i = y0i + 1 > 255 ? 255 : y0i + 1;
    int x1i = x0i + 1 > 255 ? 255 : x0i + 1;
    int base00 = (y0i * 256 + x0i) * 3;
    int base01 = (y0i * 256 + x1i) * 3;
    int base10 = (y1i * 256 + x0i) * 3;
    int base11 = (y1i * 256 + x1i) * 3;
    float omwx = __fsub_rn(1.0f, wx), omwy = __fsub_rn(1.0f, wy);
    int mbase = (y * WW + x) * 3;
    float* op = out + (size_t)b * IMG_ELEMS + mbase;
    float res[3];
#pragma unroll
    for (int c = 0; c < 3; c++) {
        float v00 = pb[base00 + c], v01 = pb[base01 + c];
        float v10 = pb[base10 + c], v11 = pb[base11 + c];
        float t0 = __fadd_rn(__fmul_rn(omwx, v00), __fmul_rn(wx, v01));
        float t1 = __fadd_rn(__fmul_rn(omwx, v10), __fmul_rn(wx, v11));
        float bil = __fadd_rn(__fmul_rn(omwy, t0), __fmul_rn(wy, t1));
        unsigned bits = rbits32(bf.kn0, bf.kn1, (unsigned)(mbase + c));
        float nz = fmaxf(-0.01f, __fadd_rn(__fmul_rn(u01f(bits), 0.02f), -0.01f));
        float val = __fadd_rn(__fadd_rn(bil, nz), bf.delta);
        res[c] = fminf(fmaxf(val, -1.0f), 1.0f);
    }
    op[0] = res[0]; op[1] = res[1]; op[2] = res[2];
}

extern "C" void kernel_launch(void* const* d_in, const int* in_sizes, int n_in,
                              void* d_out, int out_size) {
    const float *images = nullptr, *boxes = nullptr, *patch = nullptr, *scalep = nullptr;
    for (int i = 0; i < n_in; i++) {
        if      (in_sizes[i] == BB * IMG_ELEMS)  images = (const float*)d_in[i];
        else if (in_sizes[i] == BB * NBOX * 4)   boxes  = (const float*)d_in[i];
        else if (in_sizes[i] == PATCH_ELEMS)     patch  = (const float*)d_in[i];
        else if (in_sizes[i] == 1)               scalep = (const float*)d_in[i];
    }
    k_setup<<<1, 128>>>(boxes, scalep);
    k_stream<<<1280, 256>>>((const float4*)images, (float4*)d_out, patch);
    k_build<<<768, 256>>>(patch);
    k_scatter<<<BB * NBOX * 64, 256>>>((float*)d_out);
}